// round 3
// baseline (speedup 1.0000x reference)
#include <cuda_runtime.h>

typedef unsigned long long ull;

#define E_CNT 1600000
#define N_CNT 100000
#define NGRAPH 64
#define NB_SCAN ((N_CNT + 1023) / 1024)   // 98

// ---------------- device scratch ----------------
__device__ alignas(16) float g_portW[65536 * 64];   // emb_port @ W1[16:32] + b1
__device__ alignas(16) float g_flagsW[256 * 64];    // emb_flags @ W1[32:34]
__device__ alignas(16) float g_hsum[N_CNT * 64];    // sum of relu(h_pre) at col
__device__ alignas(16) float g_hpre[N_CNT * 64];    // sum of h_pre at col
__device__ float g_invdeg[N_CNT];
__device__ alignas(16) float g_md[N_CNT * 64];
__device__ alignas(16) float g_x[N_CNT * 64];
__device__ alignas(16) float g_y[N_CNT * 64];
__device__ float g_meanacc[NGRAPH * 64];
__device__ unsigned g_maxacc[NGRAPH * 64];
__device__ float g_gcnt[NGRAPH];
// CSR
__device__ int g_icnt[N_CNT];
__device__ int g_ofs[N_CNT + 1];
__device__ int g_wr[N_CNT];
__device__ int g_bsum[NB_SCAN];
__device__ int g_bbase[NB_SCAN];
__device__ alignas(16) int4 g_csr[E_CNT];           // {row, eid, port, flag}

// ---------------- packed f32x2 helpers ----------------
__device__ __forceinline__ ull pack2(float x, float y) {
    ull r; asm("mov.b64 %0,{%1,%2};" : "=l"(r) : "f"(x), "f"(y)); return r;
}
__device__ __forceinline__ ull packdup(float x) {
    ull r; asm("mov.b64 %0,{%1,%1};" : "=l"(r) : "f"(x)); return r;
}
__device__ __forceinline__ void unpack2(ull v, float& x, float& y) {
    asm("mov.b64 {%0,%1},%2;" : "=f"(x), "=f"(y) : "l"(v));
}
__device__ __forceinline__ ull fma2(ull a, ull b, ull c) {
    asm("fma.rn.f32x2 %0,%1,%2,%0;" : "+l"(c) : "l"(a), "l"(b)); return c;
}
__device__ __forceinline__ ull fma2s(float s, ull b, ull c) {
    return fma2(packdup(s), b, c);
}
__device__ __forceinline__ ull add2(ull a, ull b) {
    ull d; asm("add.rn.f32x2 %0,%1,%2;" : "=l"(d) : "l"(a), "l"(b)); return d;
}
__device__ __forceinline__ ull mul2(ull a, ull b) {
    ull d; asm("mul.rn.f32x2 %0,%1,%2;" : "=l"(d) : "l"(a), "l"(b)); return d;
}
__device__ __forceinline__ void red2f(float* p, float x, float y) {
    asm volatile("red.global.add.v2.f32 [%0],{%1,%2};" :: "l"(p), "f"(x), "f"(y) : "memory");
}
__device__ __forceinline__ unsigned fkey(float f) {
    unsigned u = __float_as_uint(f);
    return (u & 0x80000000u) ? ~u : (u | 0x80000000u);
}

// ---------------- K0a: portW = emb_port @ W1[16:32] + b1 ----------------
__global__ void __launch_bounds__(256) k_portW(const float* __restrict__ embp,
                                               const float* __restrict__ W1,
                                               const float* __restrict__ b1) {
    __shared__ alignas(16) float Wp[16 * 64];
    __shared__ alignas(16) float b1s[64];
    for (int i = threadIdx.x; i < 16 * 64; i += 256) Wp[i] = W1[16 * 64 + i];
    if (threadIdx.x < 64) b1s[threadIdx.x] = b1[threadIdx.x];
    __syncthreads();
    const int wid = threadIdx.x >> 5, L = threadIdx.x & 31;
    for (int p = blockIdx.x * 8 + wid; p < 65536; p += gridDim.x * 8) {
        float a = (L < 16) ? embp[p * 16 + L] : 0.f;
        ull acc = *(const ull*)(b1s + 2 * L);
#pragma unroll
        for (int k = 0; k < 16; k++)
            acc = fma2s(__shfl_sync(0xffffffffu, a, k), *(const ull*)(Wp + k * 64 + 2 * L), acc);
        *(ull*)(g_portW + p * 64 + 2 * L) = acc;
    }
}

// ---------------- K0b: flagsW = emb_flags @ W1[32:34] ----------------
__global__ void k_flagsW(const float* __restrict__ embf, const float* __restrict__ W1) {
    int r = blockIdx.x, j = threadIdx.x;  // grid 256, block 64
    float e0 = embf[r * 2], e1 = embf[r * 2 + 1];
    g_flagsW[r * 64 + j] = e0 * W1[32 * 64 + j] + e1 * W1[33 * 64 + j];
}

// ---------------- CSR build ----------------
__global__ void k_deg(const int* __restrict__ ei) {
    int i = blockIdx.x * blockDim.x + threadIdx.x;
    if (i * 4 < E_CNT) {
        int4 c = *(const int4*)(ei + E_CNT + i * 4);
        atomicAdd(g_icnt + c.x, 1);
        atomicAdd(g_icnt + c.y, 1);
        atomicAdd(g_icnt + c.z, 1);
        atomicAdd(g_icnt + c.w, 1);
    }
}

__global__ void k_scanA(void) {
    __shared__ int s[1024];
    const int t = threadIdx.x, idx = blockIdx.x * 1024 + t;
    int v = (idx < N_CNT) ? g_icnt[idx] : 0;
    s[t] = v;
    __syncthreads();
#pragma unroll
    for (int d = 1; d < 1024; d <<= 1) {
        int tmp = (t >= d) ? s[t - d] : 0;
        __syncthreads();
        s[t] += tmp;
        __syncthreads();
    }
    if (idx < N_CNT) g_ofs[idx] = s[t] - v;  // exclusive, pre-base
    if (t == 1023) g_bsum[blockIdx.x] = s[1023];
}

__global__ void k_scanB(void) {
    __shared__ int s[128];
    const int t = threadIdx.x;
    int v = (t < NB_SCAN) ? g_bsum[t] : 0;
    s[t] = v;
    __syncthreads();
#pragma unroll
    for (int d = 1; d < 128; d <<= 1) {
        int tmp = (t >= d) ? s[t - d] : 0;
        __syncthreads();
        s[t] += tmp;
        __syncthreads();
    }
    if (t < NB_SCAN) g_bbase[t] = s[t] - v;
    if (t == 127) g_ofs[N_CNT] = s[127];  // = E_CNT
}

__global__ void k_scanC(void) {
    int idx = blockIdx.x * blockDim.x + threadIdx.x;
    if (idx < N_CNT) {
        int o = g_ofs[idx] + g_bbase[idx >> 10];
        g_ofs[idx] = o;
        g_wr[idx] = o;
    }
}

__global__ void k_fill(const int* __restrict__ ei, const int* __restrict__ ports,
                       const int* __restrict__ flags) {
    int e = blockIdx.x * blockDim.x + threadIdx.x;
    if (e < E_CNT) {
        int col = ei[E_CNT + e];
        int p = atomicAdd(g_wr + col, 1);
        g_csr[p] = make_int4(ei[e], e, ports[e], flags[e]);
    }
}

// ---------------- K1: gather-mode edge MLP (half-warp per node) ----------------
__global__ void __launch_bounds__(256) k_gather(const float* __restrict__ eattr,
                                                const float* __restrict__ W1) {
    const int wid = threadIdx.x >> 5, L = threadIdx.x & 31;
    const int h = L >> 4, l = L & 15;
    // W1 (16x64) in registers: lane l owns output dims 4l..4l+3
    ull Wa[16], Wb[16];
#pragma unroll
    for (int k = 0; k < 16; k++) {
        float4 w = *(const float4*)(W1 + k * 64 + 4 * l);
        Wa[k] = pack2(w.x, w.y);
        Wb[k] = pack2(w.z, w.w);
    }
    const int n = (blockIdx.x * 8 + wid) * 2 + h;
    if (n >= N_CNT) return;
    const int beg = g_ofs[n], end = g_ofs[n + 1];
    ull hpa = 0ull, hpb = 0ull, hsa = 0ull, hsb = 0ull;
    for (int i = beg; i < end; i++) {
        const int4 ent = g_csr[i];                    // uniform within half-warp
        const float* ap = eattr + (size_t)ent.y * 16;
        const float4 a0 = *(const float4*)(ap + 0);
        const float4 a1 = *(const float4*)(ap + 4);
        const float4 a2 = *(const float4*)(ap + 8);
        const float4 a3 = *(const float4*)(ap + 12);
        const float4 pw = *(const float4*)(g_portW + ent.z * 64 + 4 * l);
        const float4 fw = *(const float4*)(g_flagsW + ent.w * 64 + 4 * l);
        ull acc_a = pack2(pw.x + fw.x, pw.y + fw.y);
        ull acc_b = pack2(pw.z + fw.z, pw.w + fw.w);
        acc_a = fma2s(a0.x, Wa[0], acc_a);  acc_b = fma2s(a0.x, Wb[0], acc_b);
        acc_a = fma2s(a0.y, Wa[1], acc_a);  acc_b = fma2s(a0.y, Wb[1], acc_b);
        acc_a = fma2s(a0.z, Wa[2], acc_a);  acc_b = fma2s(a0.z, Wb[2], acc_b);
        acc_a = fma2s(a0.w, Wa[3], acc_a);  acc_b = fma2s(a0.w, Wb[3], acc_b);
        acc_a = fma2s(a1.x, Wa[4], acc_a);  acc_b = fma2s(a1.x, Wb[4], acc_b);
        acc_a = fma2s(a1.y, Wa[5], acc_a);  acc_b = fma2s(a1.y, Wb[5], acc_b);
        acc_a = fma2s(a1.z, Wa[6], acc_a);  acc_b = fma2s(a1.z, Wb[6], acc_b);
        acc_a = fma2s(a1.w, Wa[7], acc_a);  acc_b = fma2s(a1.w, Wb[7], acc_b);
        acc_a = fma2s(a2.x, Wa[8], acc_a);  acc_b = fma2s(a2.x, Wb[8], acc_b);
        acc_a = fma2s(a2.y, Wa[9], acc_a);  acc_b = fma2s(a2.y, Wb[9], acc_b);
        acc_a = fma2s(a2.z, Wa[10], acc_a); acc_b = fma2s(a2.z, Wb[10], acc_b);
        acc_a = fma2s(a2.w, Wa[11], acc_a); acc_b = fma2s(a2.w, Wb[11], acc_b);
        acc_a = fma2s(a3.x, Wa[12], acc_a); acc_b = fma2s(a3.x, Wb[12], acc_b);
        acc_a = fma2s(a3.y, Wa[13], acc_a); acc_b = fma2s(a3.y, Wb[13], acc_b);
        acc_a = fma2s(a3.z, Wa[14], acc_a); acc_b = fma2s(a3.z, Wb[14], acc_b);
        acc_a = fma2s(a3.w, Wa[15], acc_a); acc_b = fma2s(a3.w, Wb[15], acc_b);
        hpa = add2(hpa, acc_a);
        hpb = add2(hpb, acc_b);
        float p0, p1, p2, p3;
        unpack2(acc_a, p0, p1);
        unpack2(acc_b, p2, p3);
        hsa = add2(hsa, pack2(fmaxf(p0, 0.f), fmaxf(p1, 0.f)));
        hsb = add2(hsb, pack2(fmaxf(p2, 0.f), fmaxf(p3, 0.f)));
    }
    ulonglong2 hp; hp.x = hpa; hp.y = hpb;
    ulonglong2 hs; hs.x = hsa; hs.y = hsb;
    *(ulonglong2*)(g_hpre + n * 64 + 4 * l) = hp;
    *(ulonglong2*)(g_hsum + n * 64 + 4 * l) = hs;
}

// ---------------- K2: node GEMM: md = (hsum + relu(h_self)) @ W2 + (cnt+1) b2 ---
__global__ void __launch_bounds__(256) k_nodes(
    const float* __restrict__ W2, const float* __restrict__ b1,
    const float* __restrict__ b2) {
    __shared__ alignas(16) float W2s[64 * 64];
    __shared__ alignas(16) float b1s[64];
    __shared__ alignas(16) float b2s[64];
    for (int i = threadIdx.x; i < 64 * 64; i += 256) W2s[i] = W2[i];
    if (threadIdx.x < 64) { b1s[threadIdx.x] = b1[threadIdx.x]; b2s[threadIdx.x] = b2[threadIdx.x]; }
    __syncthreads();
    const int wid = threadIdx.x >> 5, L = threadIdx.x & 31;
    const int n0 = (blockIdx.x * 8 + wid) * 2;
    if (n0 >= N_CNT) return;
    const int n1 = n0 + 1;
    const int o0 = g_ofs[n0], o1 = g_ofs[n1], o2 = g_ofs[n1 + 1];
    const float cnt0 = (float)(o1 - o0), cnt1 = (float)(o2 - o1);
    const float inv0 = 1.f / fmaxf(cnt0, 1.f), inv1 = 1.f / fmaxf(cnt1, 1.f);
    const float c0 = 1.f - cnt0 * inv0, c1 = 1.f - cnt1 * inv1;  // b1 correction (cnt==0 only)
    float q0x, q0y, q1x, q1y, s0x, s0y, s1x, s1y;
    unpack2(*(const ull*)(g_hpre + n0 * 64 + 2 * L), q0x, q0y);
    unpack2(*(const ull*)(g_hpre + n1 * 64 + 2 * L), q1x, q1y);
    unpack2(*(const ull*)(g_hsum + n0 * 64 + 2 * L), s0x, s0y);
    unpack2(*(const ull*)(g_hsum + n1 * 64 + 2 * L), s1x, s1y);
    const float b1a = b1s[2 * L], b1b = b1s[2 * L + 1];
    ull hh0 = pack2(s0x + fmaxf(q0x * inv0 + b1a * c0, 0.f),
                    s0y + fmaxf(q0y * inv0 + b1b * c0, 0.f));
    ull hh1 = pack2(s1x + fmaxf(q1x * inv1 + b1a * c1, 0.f),
                    s1y + fmaxf(q1y * inv1 + b1b * c1, 0.f));
    const float d0 = cnt0 + 1.f, d1 = cnt1 + 1.f;
    ull m0 = pack2(b2s[2 * L] * d0, b2s[2 * L + 1] * d0);
    ull m1 = pack2(b2s[2 * L] * d1, b2s[2 * L + 1] * d1);
#pragma unroll
    for (int kk = 0; kk < 32; kk++) {
        const ull w_a = *(const ull*)(W2s + (2 * kk) * 64 + 2 * L);
        const ull w_b = *(const ull*)(W2s + (2 * kk + 1) * 64 + 2 * L);
        const ull bb0 = __shfl_sync(0xffffffffu, hh0, kk);
        const ull bb1 = __shfl_sync(0xffffffffu, hh1, kk);
        float x0, y0, x1, y1;
        unpack2(bb0, x0, y0);
        unpack2(bb1, x1, y1);
        m0 = fma2s(x0, w_a, m0); m0 = fma2s(y0, w_b, m0);
        m1 = fma2s(x1, w_a, m1); m1 = fma2s(y1, w_b, m1);
    }
    const float invd0 = 1.f / d0, invd1 = 1.f / d1;
    *(ull*)(g_md + n0 * 64 + 2 * L) = m0;
    *(ull*)(g_md + n1 * 64 + 2 * L) = m1;
    *(ull*)(g_x + n0 * 64 + 2 * L) = mul2(m0, packdup(invd0));  // x1
    *(ull*)(g_x + n1 * 64 + 2 * L) = mul2(m1, packdup(invd1));
    if (L == 0) { g_invdeg[n0] = invd0; g_invdeg[n1] = invd1; }
}

// ---------------- K3: SpMM pass (gather): xout[n] = (xin[n]+md[n]+Σ xin[row]) * invdeg
__global__ void __launch_bounds__(256) k_spmm(const float* __restrict__ xin,
                                              float* __restrict__ xout) {
    const int wid = threadIdx.x >> 5, L = threadIdx.x & 31;
    const int h = L >> 4, l = L & 15;
    const int n = (blockIdx.x * 8 + wid) * 2 + h;
    if (n >= N_CNT) return;
    const int beg = g_ofs[n], end = g_ofs[n + 1];
    float4 acc = *(const float4*)(xin + n * 64 + 4 * l);
    const float4 m = *(const float4*)(g_md + n * 64 + 4 * l);
    acc.x += m.x; acc.y += m.y; acc.z += m.z; acc.w += m.w;
    const int* rowp = (const int*)g_csr;
    for (int i = beg; i < end; i++) {
        const int row = rowp[4 * i];                  // uniform within half-warp
        const float4 v = *(const float4*)(xin + row * 64 + 4 * l);
        acc.x += v.x; acc.y += v.y; acc.z += v.z; acc.w += v.w;
    }
    const float d = g_invdeg[n];
    acc.x *= d; acc.y *= d; acc.z *= d; acc.w *= d;
    *(float4*)(xout + n * 64 + 4 * l) = acc;
}

// ---------------- K4: pooling (x already scaled) ----------------
__global__ void __launch_bounds__(256) k_pool(const int* __restrict__ batch) {
    const int wid = threadIdx.x >> 5, L = threadIdx.x & 31;
    const int n = blockIdx.x * 8 + wid;
    if (n >= N_CNT) return;
    const int g = batch[n];
    float vx, vy;
    unpack2(*(const ull*)(g_x + n * 64 + 2 * L), vx, vy);
    red2f(g_meanacc + g * 64 + 2 * L, vx, vy);
    atomicMax(g_maxacc + g * 64 + 2 * L, fkey(vx));
    atomicMax(g_maxacc + g * 64 + 2 * L + 1, fkey(vy));
    if (L == 0) atomicAdd(g_gcnt + g, 1.f);
}

// ---------------- K5: classifier ----------------
__global__ void k_cls(const float* __restrict__ CW1, const float* __restrict__ Cb1,
                      const float* __restrict__ CW2, const float* __restrict__ Cb2,
                      float* __restrict__ out) {
    __shared__ float pooled[128];
    __shared__ float hs[64];
    const int g = blockIdx.x, j = threadIdx.x;
    float mean = g_meanacc[g * 64 + j] / fmaxf(g_gcnt[g], 1.f);
    unsigned k = g_maxacc[g * 64 + j];
    float mx = (k & 0x80000000u) ? __uint_as_float(k & 0x7FFFFFFFu) : __uint_as_float(~k);
    pooled[j] = mean;
    pooled[64 + j] = mx;
    __syncthreads();
    float hv = Cb1[j];
#pragma unroll 8
    for (int k2 = 0; k2 < 128; k2++) hv += pooled[k2] * CW1[k2 * 64 + j];
    hs[j] = fmaxf(hv, 0.f);
    __syncthreads();
    if (j < 10) {
        float o = Cb2[j];
#pragma unroll
        for (int k2 = 0; k2 < 64; k2++) o += hs[k2] * CW2[k2 * 10 + j];
        out[g * 10 + j] = o;
    }
}

// ---------------- host launcher ----------------
extern "C" void kernel_launch(void* const* d_in, const int* in_sizes, int n_in,
                              void* d_out, int out_size) {
    const int* ei      = (const int*)d_in[0];
    const int* ports   = (const int*)d_in[1];
    const int* flags   = (const int*)d_in[2];
    const float* eattr = (const float*)d_in[3];
    const int* batch   = (const int*)d_in[4];
    const float* embp  = (const float*)d_in[5];
    const float* embf  = (const float*)d_in[6];
    const float* W1    = (const float*)d_in[7];
    const float* b1    = (const float*)d_in[8];
    const float* W2    = (const float*)d_in[9];
    const float* b2    = (const float*)d_in[10];
    const float* CW1   = (const float*)d_in[11];
    const float* Cb1   = (const float*)d_in[12];
    const float* CW2   = (const float*)d_in[13];
    const float* Cb2   = (const float*)d_in[14];
    float* out = (float*)d_out;

    void *p_icnt, *p_mean, *p_max, *p_gc, *p_x, *p_y;
    cudaGetSymbolAddress(&p_icnt, g_icnt);
    cudaGetSymbolAddress(&p_mean, g_meanacc);
    cudaGetSymbolAddress(&p_max, g_maxacc);
    cudaGetSymbolAddress(&p_gc, g_gcnt);
    cudaGetSymbolAddress(&p_x, g_x);
    cudaGetSymbolAddress(&p_y, g_y);
    cudaMemsetAsync(p_icnt, 0, sizeof(int) * N_CNT);
    cudaMemsetAsync(p_mean, 0, sizeof(float) * NGRAPH * 64);
    cudaMemsetAsync(p_max, 0, sizeof(unsigned) * NGRAPH * 64);
    cudaMemsetAsync(p_gc, 0, sizeof(float) * NGRAPH);

    k_portW<<<1024, 256>>>(embp, W1, b1);
    k_flagsW<<<256, 64>>>(embf, W1);
    // CSR build
    k_deg<<<(E_CNT / 4 + 255) / 256, 256>>>(ei);
    k_scanA<<<NB_SCAN, 1024>>>();
    k_scanB<<<1, 128>>>();
    k_scanC<<<(N_CNT + 255) / 256, 256>>>();
    k_fill<<<(E_CNT + 255) / 256, 256>>>(ei, ports, flags);
    // edge MLP (gather mode) + node GEMM
    k_gather<<<(N_CNT / 2 + 7) / 8, 256>>>(eattr, W1);
    k_nodes<<<(N_CNT / 2 + 7) / 8, 256>>>(W2, b1, b2);
    // two SpMM passes: x1 -> x2 -> x3
    k_spmm<<<(N_CNT / 2 + 7) / 8, 256>>>((const float*)p_x, (float*)p_y);
    k_spmm<<<(N_CNT / 2 + 7) / 8, 256>>>((const float*)p_y, (float*)p_x);
    k_pool<<<(N_CNT + 7) / 8, 256>>>(batch);
    k_cls<<<NGRAPH, 64>>>(CW1, Cb1, CW2, Cb2, out);
}

// round 4
// speedup vs baseline: 1.2085x; 1.2085x over previous
#include <cuda_runtime.h>

typedef unsigned long long ull;

#define E_CNT 1600000
#define N_CNT 100000
#define NGRAPH 64
#define NB_SCAN ((N_CNT + 1023) / 1024)   // 98

// ---------------- device scratch ----------------
__device__ alignas(16) float g_portW[65536 * 64];   // emb_port @ W1[16:32] + b1
__device__ alignas(16) float g_flagsW[256 * 64];    // emb_flags @ W1[32:34]
__device__ float g_invdeg[N_CNT];
__device__ alignas(16) float g_md[N_CNT * 64];
__device__ alignas(16) float g_x[N_CNT * 64];
__device__ alignas(16) float g_y[N_CNT * 64];
__device__ float g_meanacc[NGRAPH * 64];
__device__ unsigned g_maxacc[NGRAPH * 64];
__device__ float g_gcnt[NGRAPH];
// CSR
__device__ int g_icnt[N_CNT];
__device__ int g_ofs[N_CNT + 1];
__device__ int g_wr[N_CNT];
__device__ int g_bsum[NB_SCAN];
__device__ ull g_epf[E_CNT];    // {hi: port*256+flag, lo: eid}
__device__ int g_row[E_CNT];

// ---------------- packed f32x2 helpers ----------------
__device__ __forceinline__ ull pack2(float x, float y) {
    ull r; asm("mov.b64 %0,{%1,%2};" : "=l"(r) : "f"(x), "f"(y)); return r;
}
__device__ __forceinline__ ull packdup(float x) {
    ull r; asm("mov.b64 %0,{%1,%1};" : "=l"(r) : "f"(x)); return r;
}
__device__ __forceinline__ void unpack2(ull v, float& x, float& y) {
    asm("mov.b64 {%0,%1},%2;" : "=f"(x), "=f"(y) : "l"(v));
}
__device__ __forceinline__ ull fma2(ull a, ull b, ull c) {
    asm("fma.rn.f32x2 %0,%1,%2,%0;" : "+l"(c) : "l"(a), "l"(b)); return c;
}
__device__ __forceinline__ ull fma2s(float s, ull b, ull c) {
    return fma2(packdup(s), b, c);
}
__device__ __forceinline__ ull add2(ull a, ull b) {
    ull d; asm("add.rn.f32x2 %0,%1,%2;" : "=l"(d) : "l"(a), "l"(b)); return d;
}
__device__ __forceinline__ ull mul2(ull a, ull b) {
    ull d; asm("mul.rn.f32x2 %0,%1,%2;" : "=l"(d) : "l"(a), "l"(b)); return d;
}
__device__ __forceinline__ void red4f(float* p, float a, float b, float c, float d) {
    asm volatile("red.global.add.v4.f32 [%0],{%1,%2,%3,%4};"
                 :: "l"(p), "f"(a), "f"(b), "f"(c), "f"(d) : "memory");
}
__device__ __forceinline__ unsigned fkey(float f) {
    unsigned u = __float_as_uint(f);
    return (u & 0x80000000u) ? ~u : (u | 0x80000000u);
}

// ---------------- K0: prep = portW + flagsW + degree count ----------------
#define DEG_BLKS ((E_CNT / 4 + 255) / 256)
__global__ void __launch_bounds__(256) k_prep(const float* __restrict__ embp,
                                              const float* __restrict__ embf,
                                              const float* __restrict__ W1,
                                              const float* __restrict__ b1,
                                              const int* __restrict__ ei) {
    const int b = blockIdx.x;
    if (b < 1024) {  // portW = emb_port @ W1[16:32] + b1
        __shared__ alignas(16) float Wp[16 * 64];
        __shared__ alignas(16) float b1s[64];
        for (int i = threadIdx.x; i < 16 * 64; i += 256) Wp[i] = W1[16 * 64 + i];
        if (threadIdx.x < 64) b1s[threadIdx.x] = b1[threadIdx.x];
        __syncthreads();
        const int wid = threadIdx.x >> 5, L = threadIdx.x & 31;
        for (int p = b * 8 + wid; p < 65536; p += 8192) {
            float a = (L < 16) ? embp[p * 16 + L] : 0.f;
            ull acc = *(const ull*)(b1s + 2 * L);
#pragma unroll
            for (int k = 0; k < 16; k++)
                acc = fma2s(__shfl_sync(0xffffffffu, a, k), *(const ull*)(Wp + k * 64 + 2 * L), acc);
            *(ull*)(g_portW + p * 64 + 2 * L) = acc;
        }
    } else if (b < 1088) {  // flagsW = emb_flags @ W1[32:34]
        const int idx = (b - 1024) * 256 + threadIdx.x;  // 16384 = 256*64
        const int r = idx >> 6, j = idx & 63;
        g_flagsW[idx] = embf[r * 2] * W1[32 * 64 + j] + embf[r * 2 + 1] * W1[33 * 64 + j];
    } else {  // degree count (by col)
        const int i = (b - 1088) * 256 + threadIdx.x;
        if (i < E_CNT / 4) {
            int4 c = *(const int4*)(ei + E_CNT + i * 4);
            atomicAdd(g_icnt + c.x, 1);
            atomicAdd(g_icnt + c.y, 1);
            atomicAdd(g_icnt + c.z, 1);
            atomicAdd(g_icnt + c.w, 1);
        }
    }
}

// ---------------- CSR scan ----------------
__global__ void k_scanA(void) {
    __shared__ int s[1024];
    const int t = threadIdx.x, idx = blockIdx.x * 1024 + t;
    int v = (idx < N_CNT) ? g_icnt[idx] : 0;
    s[t] = v;
    __syncthreads();
#pragma unroll
    for (int d = 1; d < 1024; d <<= 1) {
        int tmp = (t >= d) ? s[t - d] : 0;
        __syncthreads();
        s[t] += tmp;
        __syncthreads();
    }
    if (idx < N_CNT) g_ofs[idx] = s[t] - v;  // exclusive, pre-base
    if (t == 1023) g_bsum[blockIdx.x] = s[1023];
}

__global__ void k_scanBC(void) {
    __shared__ int bs[NB_SCAN];
    __shared__ int bb[NB_SCAN + 1];
    const int t = threadIdx.x;
    if (t < NB_SCAN) bs[t] = g_bsum[t];
    __syncthreads();
    if (t == 0) {
        int s = 0;
#pragma unroll 7
        for (int i = 0; i < NB_SCAN; i++) { bb[i] = s; s += bs[i]; }
        bb[NB_SCAN] = s;
    }
    __syncthreads();
    const int idx = blockIdx.x * 1024 + t;
    if (idx < N_CNT) {
        int o = g_ofs[idx] + bb[blockIdx.x];
        g_ofs[idx] = o;
        g_wr[idx] = o;
    }
    if (blockIdx.x == 0 && t == 0) g_ofs[N_CNT] = bb[NB_SCAN];  // = E_CNT
}

// ---------------- K-fill: CSR fill (SoA: epf + row) ----------------
__global__ void k_fill(const int* __restrict__ ei, const int* __restrict__ ports,
                       const int* __restrict__ flags) {
    int e = blockIdx.x * blockDim.x + threadIdx.x;
    if (e < E_CNT) {
        int col = ei[E_CNT + e];
        int p = atomicAdd(g_wr + col, 1);
        unsigned pf = ((unsigned)ports[e] << 8) | (unsigned)flags[e];
        g_epf[p] = ((ull)pf << 32) | (unsigned)e;
        g_row[p] = ei[e];
    }
}

// ---------------- K1: fused gather (edge layer-1) + node W2 GEMM ----------------
// half-warp per node; lane l owns output dims 4l..4l+3
__global__ void __launch_bounds__(128) k_gather(
    const float* __restrict__ eattr, const float* __restrict__ W1,
    const float* __restrict__ W2, const float* __restrict__ b1,
    const float* __restrict__ b2) {
    __shared__ alignas(16) float W2s[64 * 64];
    __shared__ alignas(16) float b1s[64];
    __shared__ alignas(16) float b2s[64];
    for (int i = threadIdx.x; i < 64 * 64; i += 128) W2s[i] = W2[i];
    if (threadIdx.x < 64) { b1s[threadIdx.x] = b1[threadIdx.x]; b2s[threadIdx.x] = b2[threadIdx.x]; }
    __syncthreads();
    const int wid = threadIdx.x >> 5, L = threadIdx.x & 31;
    const int h = L >> 4, l = L & 15;
    ull Wa[16], Wb[16];
#pragma unroll
    for (int k = 0; k < 16; k++) {
        float4 w = *(const float4*)(W1 + k * 64 + 4 * l);
        Wa[k] = pack2(w.x, w.y);
        Wb[k] = pack2(w.z, w.w);
    }
    const int base = (blockIdx.x * 4 + wid) * 2;
    if (base >= N_CNT) return;
    const int n = base + h;
    const int beg = g_ofs[n], end = g_ofs[n + 1];
    ull hpa = 0ull, hpb = 0ull, hsa = 0ull, hsb = 0ull;
    for (int i = beg; i < end; i++) {
        const ull epf = g_epf[i];                     // uniform within half-warp
        const int eid = (int)(unsigned)epf;
        const unsigned pf = (unsigned)(epf >> 32);
        const float* ap = eattr + (size_t)eid * 16;
        const float4 a0 = *(const float4*)(ap + 0);
        const float4 a1 = *(const float4*)(ap + 4);
        const float4 a2 = *(const float4*)(ap + 8);
        const float4 a3 = *(const float4*)(ap + 12);
        const float4 pw = *(const float4*)(g_portW + (pf >> 8) * 64 + 4 * l);
        const float4 fw = *(const float4*)(g_flagsW + (pf & 255u) * 64 + 4 * l);
        ull acc_a = pack2(pw.x + fw.x, pw.y + fw.y);
        ull acc_b = pack2(pw.z + fw.z, pw.w + fw.w);
        acc_a = fma2s(a0.x, Wa[0], acc_a);  acc_b = fma2s(a0.x, Wb[0], acc_b);
        acc_a = fma2s(a0.y, Wa[1], acc_a);  acc_b = fma2s(a0.y, Wb[1], acc_b);
        acc_a = fma2s(a0.z, Wa[2], acc_a);  acc_b = fma2s(a0.z, Wb[2], acc_b);
        acc_a = fma2s(a0.w, Wa[3], acc_a);  acc_b = fma2s(a0.w, Wb[3], acc_b);
        acc_a = fma2s(a1.x, Wa[4], acc_a);  acc_b = fma2s(a1.x, Wb[4], acc_b);
        acc_a = fma2s(a1.y, Wa[5], acc_a);  acc_b = fma2s(a1.y, Wb[5], acc_b);
        acc_a = fma2s(a1.z, Wa[6], acc_a);  acc_b = fma2s(a1.z, Wb[6], acc_b);
        acc_a = fma2s(a1.w, Wa[7], acc_a);  acc_b = fma2s(a1.w, Wb[7], acc_b);
        acc_a = fma2s(a2.x, Wa[8], acc_a);  acc_b = fma2s(a2.x, Wb[8], acc_b);
        acc_a = fma2s(a2.y, Wa[9], acc_a);  acc_b = fma2s(a2.y, Wb[9], acc_b);
        acc_a = fma2s(a2.z, Wa[10], acc_a); acc_b = fma2s(a2.z, Wb[10], acc_b);
        acc_a = fma2s(a2.w, Wa[11], acc_a); acc_b = fma2s(a2.w, Wb[11], acc_b);
        acc_a = fma2s(a3.x, Wa[12], acc_a); acc_b = fma2s(a3.x, Wb[12], acc_b);
        acc_a = fma2s(a3.y, Wa[13], acc_a); acc_b = fma2s(a3.y, Wb[13], acc_b);
        acc_a = fma2s(a3.z, Wa[14], acc_a); acc_b = fma2s(a3.z, Wb[14], acc_b);
        acc_a = fma2s(a3.w, Wa[15], acc_a); acc_b = fma2s(a3.w, Wb[15], acc_b);
        hpa = add2(hpa, acc_a);
        hpb = add2(hpb, acc_b);
        float p0, p1, p2, p3;
        unpack2(acc_a, p0, p1);
        unpack2(acc_b, p2, p3);
        hsa = add2(hsa, pack2(fmaxf(p0, 0.f), fmaxf(p1, 0.f)));
        hsb = add2(hsb, pack2(fmaxf(p2, 0.f), fmaxf(p3, 0.f)));
    }
    // ---- node combine: hh = hsum + relu(hpre/cnt + b1*[cnt==0]) ----
    const float cnt = (float)(end - beg);
    const float inv = 1.f / fmaxf(cnt, 1.f);
    const float c = 1.f - cnt * inv;               // 1 iff cnt==0
    float q0, q1, q2, q3, s0, s1, s2, s3;
    unpack2(hpa, q0, q1); unpack2(hpb, q2, q3);
    unpack2(hsa, s0, s1); unpack2(hsb, s2, s3);
    const ull hh0 = pack2(s0 + fmaxf(q0 * inv + b1s[4 * l + 0] * c, 0.f),
                          s1 + fmaxf(q1 * inv + b1s[4 * l + 1] * c, 0.f));
    const ull hh1 = pack2(s2 + fmaxf(q2 * inv + b1s[4 * l + 2] * c, 0.f),
                          s3 + fmaxf(q3 * inv + b1s[4 * l + 3] * c, 0.f));
    // ---- W2 GEMM within half-warp ----
    const float d = cnt + 1.f;
    ull m0 = pack2(b2s[4 * l] * d, b2s[4 * l + 1] * d);
    ull m1 = pack2(b2s[4 * l + 2] * d, b2s[4 * l + 3] * d);
#pragma unroll
    for (int kk = 0; kk < 16; kk++) {
        const ull t0 = __shfl_sync(0xffffffffu, hh0, kk, 16);
        const ull t1 = __shfl_sync(0xffffffffu, hh1, kk, 16);
        float x0, x1, x2, x3;
        unpack2(t0, x0, x1);
        unpack2(t1, x2, x3);
        const float* wr = W2s + (4 * kk) * 64 + 4 * l;
        m0 = fma2s(x0, *(const ull*)(wr), m0);       m1 = fma2s(x0, *(const ull*)(wr + 2), m1);
        m0 = fma2s(x1, *(const ull*)(wr + 64), m0);  m1 = fma2s(x1, *(const ull*)(wr + 66), m1);
        m0 = fma2s(x2, *(const ull*)(wr + 128), m0); m1 = fma2s(x2, *(const ull*)(wr + 130), m1);
        m0 = fma2s(x3, *(const ull*)(wr + 192), m0); m1 = fma2s(x3, *(const ull*)(wr + 194), m1);
    }
    const float invd = 1.f / d;
    ulonglong2 mv; mv.x = m0; mv.y = m1;
    *(ulonglong2*)(g_md + n * 64 + 4 * l) = mv;
    ulonglong2 xv; xv.x = mul2(m0, packdup(invd)); xv.y = mul2(m1, packdup(invd));
    *(ulonglong2*)(g_x + n * 64 + 4 * l) = xv;
    if (l == 0) g_invdeg[n] = invd;
}

// ---------------- K3: SpMM pass 1: y[n] = (x[n]+md[n]+Σ x[row]) * invdeg ----------------
__global__ void __launch_bounds__(256) k_spmm(const float* __restrict__ xin,
                                              float* __restrict__ xout) {
    const int wid = threadIdx.x >> 5, L = threadIdx.x & 31;
    const int h = L >> 4, l = L & 15;
    const int n = (blockIdx.x * 8 + wid) * 2 + h;
    if (n >= N_CNT) return;
    const int beg = g_ofs[n], end = g_ofs[n + 1];
    float4 acc = *(const float4*)(xin + n * 64 + 4 * l);
    const float4 m = *(const float4*)(g_md + n * 64 + 4 * l);
    acc.x += m.x; acc.y += m.y; acc.z += m.z; acc.w += m.w;
    for (int i = beg; i < end; i++) {
        const int row = g_row[i];                    // uniform within half-warp
        const float4 v = *(const float4*)(xin + row * 64 + 4 * l);
        acc.x += v.x; acc.y += v.y; acc.z += v.z; acc.w += v.w;
    }
    const float d = g_invdeg[n];
    acc.x *= d; acc.y *= d; acc.z *= d; acc.w *= d;
    *(float4*)(xout + n * 64 + 4 * l) = acc;
}

// ---------------- K4: SpMM pass 2 fused with pooling (x3 never stored) ----------------
__global__ void __launch_bounds__(256) k_spmm_pool(const float* __restrict__ xin,
                                                   const int* __restrict__ batch) {
    const int wid = threadIdx.x >> 5, L = threadIdx.x & 31;
    const int h = L >> 4, l = L & 15;
    const int n = (blockIdx.x * 8 + wid) * 2 + h;
    if (n >= N_CNT) return;
    const int beg = g_ofs[n], end = g_ofs[n + 1];
    float4 acc = *(const float4*)(xin + n * 64 + 4 * l);
    const float4 m = *(const float4*)(g_md + n * 64 + 4 * l);
    acc.x += m.x; acc.y += m.y; acc.z += m.z; acc.w += m.w;
    for (int i = beg; i < end; i++) {
        const int row = g_row[i];
        const float4 v = *(const float4*)(xin + row * 64 + 4 * l);
        acc.x += v.x; acc.y += v.y; acc.z += v.z; acc.w += v.w;
    }
    const float d = g_invdeg[n];
    acc.x *= d; acc.y *= d; acc.z *= d; acc.w *= d;
    const int g = batch[n];
    red4f(g_meanacc + g * 64 + 4 * l, acc.x, acc.y, acc.z, acc.w);
    unsigned* mp = g_maxacc + g * 64 + 4 * l;
    atomicMax(mp + 0, fkey(acc.x));
    atomicMax(mp + 1, fkey(acc.y));
    atomicMax(mp + 2, fkey(acc.z));
    atomicMax(mp + 3, fkey(acc.w));
    if (l == 0) atomicAdd(g_gcnt + g, 1.f);
}

// ---------------- K5: classifier ----------------
__global__ void k_cls(const float* __restrict__ CW1, const float* __restrict__ Cb1,
                      const float* __restrict__ CW2, const float* __restrict__ Cb2,
                      float* __restrict__ out) {
    __shared__ float pooled[128];
    __shared__ float hs[64];
    const int g = blockIdx.x, j = threadIdx.x;
    float mean = g_meanacc[g * 64 + j] / fmaxf(g_gcnt[g], 1.f);
    unsigned k = g_maxacc[g * 64 + j];
    float mx = (k & 0x80000000u) ? __uint_as_float(k & 0x7FFFFFFFu) : __uint_as_float(~k);
    pooled[j] = mean;
    pooled[64 + j] = mx;
    __syncthreads();
    float hv = Cb1[j];
#pragma unroll 8
    for (int k2 = 0; k2 < 128; k2++) hv += pooled[k2] * CW1[k2 * 64 + j];
    hs[j] = fmaxf(hv, 0.f);
    __syncthreads();
    if (j < 10) {
        float o = Cb2[j];
#pragma unroll
        for (int k2 = 0; k2 < 64; k2++) o += hs[k2] * CW2[k2 * 10 + j];
        out[g * 10 + j] = o;
    }
}

// ---------------- host launcher ----------------
extern "C" void kernel_launch(void* const* d_in, const int* in_sizes, int n_in,
                              void* d_out, int out_size) {
    const int* ei      = (const int*)d_in[0];
    const int* ports   = (const int*)d_in[1];
    const int* flags   = (const int*)d_in[2];
    const float* eattr = (const float*)d_in[3];
    const int* batch   = (const int*)d_in[4];
    const float* embp  = (const float*)d_in[5];
    const float* embf  = (const float*)d_in[6];
    const float* W1    = (const float*)d_in[7];
    const float* b1    = (const float*)d_in[8];
    const float* W2    = (const float*)d_in[9];
    const float* b2    = (const float*)d_in[10];
    const float* CW1   = (const float*)d_in[11];
    const float* Cb1   = (const float*)d_in[12];
    const float* CW2   = (const float*)d_in[13];
    const float* Cb2   = (const float*)d_in[14];
    float* out = (float*)d_out;

    void *p_icnt, *p_mean, *p_max, *p_gc, *p_x, *p_y;
    cudaGetSymbolAddress(&p_icnt, g_icnt);
    cudaGetSymbolAddress(&p_mean, g_meanacc);
    cudaGetSymbolAddress(&p_max, g_maxacc);
    cudaGetSymbolAddress(&p_gc, g_gcnt);
    cudaGetSymbolAddress(&p_x, g_x);
    cudaGetSymbolAddress(&p_y, g_y);
    cudaMemsetAsync(p_icnt, 0, sizeof(int) * N_CNT);
    cudaMemsetAsync(p_mean, 0, sizeof(float) * NGRAPH * 64);
    cudaMemsetAsync(p_max, 0, sizeof(unsigned) * NGRAPH * 64);
    cudaMemsetAsync(p_gc, 0, sizeof(float) * NGRAPH);

    k_prep<<<1088 + DEG_BLKS, 256>>>(embp, embf, W1, b1, ei);   // (1)
    k_scanA<<<NB_SCAN, 1024>>>();                               // (2)
    k_scanBC<<<NB_SCAN, 1024>>>();                              // (3)
    k_fill<<<(E_CNT + 255) / 256, 256>>>(ei, ports, flags);     // (4) <- ncu capture slot
    k_gather<<<(N_CNT / 2 + 3) / 4, 128>>>(eattr, W1, W2, b1, b2);  // (5)
    k_spmm<<<(N_CNT / 2 + 7) / 8, 256>>>((const float*)p_x, (float*)p_y);       // (6)
    k_spmm_pool<<<(N_CNT / 2 + 7) / 8, 256>>>((const float*)p_y, batch);        // (7)
    k_cls<<<NGRAPH, 64>>>(CW1, Cb1, CW2, Cb2, out);             // (8)
}